// round 5
// baseline (speedup 1.0000x reference)
#include <cuda_runtime.h>

// FFT convolution (S4): y[b,0,h,:] = first 4096 samples of linear conv(x[b,h,:], k[0,h,:])
// via length-8192 real FFT implemented as 4096-pt complex FFT with even/odd packing.
//
// R4: per-stage closed-form swizzled addressing (S ^ const / S + const) — removes the
// per-access SW() recomputation that dominated the issue-bound instruction stream.

#define M 4096            // complex FFT size (real size n = 2*M = 8192)
#define H 1024
#define B 4
#define NT 256
#define KSTRIDE (M + 1)   // 4096 position-major bins + bin M

// Bank swizzle: bijection on [0,4096); conflict-free for strides 1/8/64/512 (LDS.64)
#define SW(i) ((i) ^ (((i) >> 3) & 7) ^ ((((i) >> 6) & 3) << 3))

__device__ float2 g_twm[M];            // e^{-2pi i e / M}
__device__ float2 g_twnR[M / 2];       // twn[rev8(expand(t))], t = 0..2047
__device__ float2 g_Kf[H * KSTRIDE];   // position-major: g_Kf[h][p] = K_f[h][rev8(p)]; [4096] = bin M

__device__ __forceinline__ float2 cadd(float2 a, float2 b) { return make_float2(a.x + b.x, a.y + b.y); }
__device__ __forceinline__ float2 csub(float2 a, float2 b) { return make_float2(a.x - b.x, a.y - b.y); }
__device__ __forceinline__ float2 cmul(float2 a, float2 b) {
    return make_float2(fmaf(a.x, b.x, -a.y * b.y), fmaf(a.x, b.y, a.y * b.x));
}
// a * conj(b)
__device__ __forceinline__ float2 cmulc(float2 a, float2 b) {
    return make_float2(fmaf(a.x, b.x, a.y * b.y), fmaf(a.y, b.x, -a.x * b.y));
}

// base-8 digit reversal of a 12-bit index (4 digits)
__device__ __forceinline__ int rev8(int v) {
    return ((v & 7) << 9) | (((v >> 3) & 7) << 6) | (((v >> 6) & 7) << 3) | ((v >> 9) & 7);
}
// insert a 0 at bit 2: primary positions (kk < 2048 <=> p&4 == 0)
__device__ __forceinline__ int expandp(int t) { return (t & 3) | ((t >> 2) << 3); }

__global__ void init_twiddles() {
    int i = blockIdx.x * blockDim.x + threadIdx.x;
    if (i < M) {
        float s, c;
        sincospif(-2.0f * (float)i / (float)M, &s, &c);
        g_twm[i] = make_float2(c, s);
    }
    int t = i - M;
    if (t >= 0 && t < M / 2) {
        int kk = rev8(expandp(t));
        float s, c;
        sincospif(-(float)kk / (float)M, &s, &c);   // e^{-2 pi i kk / (2M)}
        g_twnR[t] = make_float2(c, s);
    }
}

#define CC 0.70710678118654752f

// One radix-8 stage. FWD: DIF (L = 4096,512,64,8). !FWD: DIT inverse (L = 8,64,512,4096).
// PIN:  (fwd, L=4096 only) inputs at indices >= 2048 are zero and are not loaded.
// POUT: (inv, L=4096 only) outputs at indices >= 2048 are discarded and not stored.
//
// Swizzled addresses computed in closed form per stage (S derived once per butterfly):
//   L=4096: SW(j+512k)            = SW(j) + 512k
//   L=512:  SW(512b+j+64k)        = ((512b + j ^ ((j>>3)&7)) ^ ((k&3)<<3)) + 64k
//   L=64:   SW(64b+j+8k)          = ((64b + j) ^ ((b&3)<<3)) ^ 9k
//   L=8:    SW(8b+k)              = (8b ^ (b&7) ^ (((b>>3)&3)<<3)) ^ k
template <int L, bool FWD, bool PIN = false, bool POUT = false>
__device__ __forceinline__ void stage8(float2* __restrict__ z, int tid) {
    constexpr int twstep = M / L;
#pragma unroll
    for (int it = 0; it < (M / 8) / NT; it++) {
        int i = tid + it * NT;
        int j, s[8];
        if (L == 4096) {
            j = i;
            int S = j ^ ((j >> 3) & 7) ^ (((j >> 6) & 3) << 3);
#pragma unroll
            for (int k = 0; k < 8; k++) s[k] = S + 512 * k;
        } else if (L == 512) {
            int b = i >> 6;
            j = i & 63;
            int S = (b * 512 + (j ^ ((j >> 3) & 7)));
#pragma unroll
            for (int k = 0; k < 8; k++) s[k] = (S ^ ((k & 3) << 3)) + 64 * k;
        } else if (L == 64) {
            int b = i >> 3;
            j = i & 7;
            int S = (b * 64 + j) ^ ((b & 3) << 3);
#pragma unroll
            for (int k = 0; k < 8; k++) s[k] = S ^ (9 * k);
        } else {  // L == 8
            int b = i;
            j = 0;
            int S = (8 * b) ^ (b & 7) ^ (((b >> 3) & 3) << 3);
#pragma unroll
            for (int k = 0; k < 8; k++) s[k] = S ^ k;
        }

        float2 a0 = z[s[0]];
        float2 a1 = z[s[1]];
        float2 a2 = z[s[2]];
        float2 a3 = z[s[3]];
        float2 a4, a5, a6, a7;
        if (!PIN) {
            a4 = z[s[4]];
            a5 = z[s[5]];
            a6 = z[s[6]];
            a7 = z[s[7]];
        }

        if (FWD) {
            float2 E0, E1, E2, E3, O0, O1, O2, O3;
            if (PIN) {
                // a4..a7 == 0
                E0 = cadd(a0, a2);
                E2 = csub(a0, a2);
                E1 = make_float2(a0.x + a2.y, a0.y - a2.x);   // a0 - i a2
                E3 = make_float2(a0.x - a2.y, a0.y + a2.x);   // a0 + i a2
                O0 = cadd(a1, a3);
                O2 = csub(a1, a3);
                O1 = make_float2(a1.x + a3.y, a1.y - a3.x);
                O3 = make_float2(a1.x - a3.y, a1.y + a3.x);
            } else {
                float2 s0 = cadd(a0, a4), s1 = csub(a0, a4), s2 = cadd(a2, a6), s3 = csub(a2, a6);
                E0 = cadd(s0, s2); E2 = csub(s0, s2);
                E1 = make_float2(s1.x + s3.y, s1.y - s3.x);   // s1 - i s3
                E3 = make_float2(s1.x - s3.y, s1.y + s3.x);   // s1 + i s3
                float2 t0 = cadd(a1, a5), t1 = csub(a1, a5), t2 = cadd(a3, a7), t3 = csub(a3, a7);
                O0 = cadd(t0, t2); O2 = csub(t0, t2);
                O1 = make_float2(t1.x + t3.y, t1.y - t3.x);
                O3 = make_float2(t1.x - t3.y, t1.y + t3.x);
            }
            float2 P1 = make_float2(CC * (O1.x + O1.y), CC * (O1.y - O1.x));   // w8^1*O1
            float2 P2 = make_float2(O2.y, -O2.x);                              // w8^2*O2
            float2 P3 = make_float2(CC * (O3.y - O3.x), -CC * (O3.x + O3.y));  // w8^3*O3
            float2 y0 = cadd(E0, O0), y4 = csub(E0, O0);
            float2 y1 = cadd(E1, P1), y5 = csub(E1, P1);
            float2 y2 = cadd(E2, P2), y6 = csub(E2, P2);
            float2 y3 = cadd(E3, P3), y7 = csub(E3, P3);
            if (L > 8) {  // twiddles (L==8 has j==0 -> all ones)
                float2 w1 = g_twm[j * twstep];
                float2 w2 = cmul(w1, w1);
                float2 w3 = cmul(w2, w1);
                float2 w4 = cmul(w2, w2);
                float2 w5 = cmul(w4, w1);
                float2 w6 = cmul(w4, w2);
                float2 w7 = cmul(w4, w3);
                y1 = cmul(y1, w1); y2 = cmul(y2, w2); y3 = cmul(y3, w3);
                y4 = cmul(y4, w4); y5 = cmul(y5, w5); y6 = cmul(y6, w6); y7 = cmul(y7, w7);
            }
            z[s[0]] = y0;
            z[s[1]] = y1;
            z[s[2]] = y2;
            z[s[3]] = y3;
            z[s[4]] = y4;
            z[s[5]] = y5;
            z[s[6]] = y6;
            z[s[7]] = y7;
        } else {
            if (L > 8) {  // conjugate twiddles before the butterfly
                float2 w1 = g_twm[j * twstep];
                float2 w2 = cmul(w1, w1);
                float2 w3 = cmul(w2, w1);
                float2 w4 = cmul(w2, w2);
                float2 w5 = cmul(w4, w1);
                float2 w6 = cmul(w4, w2);
                float2 w7 = cmul(w4, w3);
                a1 = cmulc(a1, w1); a2 = cmulc(a2, w2); a3 = cmulc(a3, w3);
                a4 = cmulc(a4, w4); a5 = cmulc(a5, w5); a6 = cmulc(a6, w6); a7 = cmulc(a7, w7);
            }
            float2 s0 = cadd(a0, a4), s1 = csub(a0, a4), s2 = cadd(a2, a6), s3 = csub(a2, a6);
            float2 E0 = cadd(s0, s2), E2 = csub(s0, s2);
            float2 E1 = make_float2(s1.x - s3.y, s1.y + s3.x);   // s1 + i s3
            float2 E3 = make_float2(s1.x + s3.y, s1.y - s3.x);   // s1 - i s3
            float2 t0 = cadd(a1, a5), t1 = csub(a1, a5), t2 = cadd(a3, a7), t3 = csub(a3, a7);
            float2 O0 = cadd(t0, t2), O2 = csub(t0, t2);
            float2 O1 = make_float2(t1.x - t3.y, t1.y + t3.x);
            float2 O3 = make_float2(t1.x + t3.y, t1.y - t3.x);
            float2 P1 = make_float2(CC * (O1.x - O1.y), CC * (O1.x + O1.y));   // v8^1*O1
            float2 P2 = make_float2(-O2.y, O2.x);                              // v8^2*O2
            float2 P3 = make_float2(-CC * (O3.x + O3.y), CC * (O3.x - O3.y));  // v8^3*O3
            z[s[0]] = cadd(E0, O0);
            z[s[1]] = cadd(E1, P1);
            z[s[2]] = cadd(E2, P2);
            z[s[3]] = cadd(E3, P3);
            if (!POUT) {
                z[s[4]] = csub(E0, O0);
                z[s[5]] = csub(E1, P1);
                z[s[6]] = csub(E2, P2);
                z[s[7]] = csub(E3, P3);
            }
        }
    }
    __syncthreads();
}

__device__ __forceinline__ void fft_fwd(float2* z, int tid) {
    stage8<4096, true, true>(z, tid);   // upper half of input is zero
    stage8<512, true>(z, tid);
    stage8<64, true>(z, tid);
    stage8<8, true>(z, tid);
}

__device__ __forceinline__ void fft_inv(float2* z, int tid) {
    stage8<8, false>(z, tid);
    stage8<64, false>(z, tid);
    stage8<512, false>(z, tid);
    stage8<4096, false, false, true>(z, tid);  // upper half of output discarded
}

// load packed real row (x[2j], x[2j+1]) -> z[j]; upper half left untouched (pruned)
__device__ __forceinline__ void load_packed(float2* z, const float* src, int tid) {
    const float4* s4 = (const float4*)src;
    for (int j = tid; j < M / 4; j += NT) {
        float4 v = s4[j];
        z[SW(2 * j)]     = make_float2(v.x, v.y);
        z[SW(2 * j + 1)] = make_float2(v.z, v.w);
    }
    __syncthreads();
}

// ---------------- kernel spectra (position-major layout) -------------------------------
__global__ __launch_bounds__(NT, 4) void kf_kernel(const float* __restrict__ kin) {
    __shared__ float2 z[M];
    const int h = blockIdx.x;
    const int tid = threadIdx.x;
    load_packed(z, kin + (size_t)h * M, tid);
    fft_fwd(z, tid);

    float2* Kh = g_Kf + (size_t)h * KSTRIDE;
    // boundary: kk ≡ 0 (mod 8)  (positions p < 512)
    {
        int t = tid;
        if (t == 0) {
            float2 Z0 = z[0];                      // SW(0)==0
            Kh[0]    = make_float2(Z0.x + Z0.y, 0.f);   // K_f[0]
            Kh[M]    = make_float2(Z0.x - Z0.y, 0.f);   // K_f[M]
            float2 Zh = z[SW(4)];                  // rev8(2048)==4
            Kh[4] = make_float2(Zh.x, -Zh.y);      // K_f[M/2] = conj(Z[M/2])
        } else {
            int kk = 8 * t;
            int pa = rev8(kk), pb = rev8(M - kk);
            float2 Zk = z[SW(pa)], Zm = z[SW(pb)];
            float2 E = make_float2(0.5f * (Zk.x + Zm.x), 0.5f * (Zk.y - Zm.y));
            float2 D = make_float2(Zk.x - Zm.x, Zk.y + Zm.y);
            float2 O = make_float2(0.5f * D.y, -0.5f * D.x);
            float2 OT = cmul(O, g_twm[4 * t]);     // twn[8t] == g_twm[4t]
            float2 X1  = cadd(E, OT);
            float2 X2c = csub(E, OT);
            Kh[pa] = X1;                           // K_f[kk]
            Kh[pb] = make_float2(X2c.x, -X2c.y);   // K_f[M-kk]
        }
    }
    // main: positions p >= 512, partner p2 = 4607 - p (conflict-free)
#pragma unroll
    for (int i2 = 1; i2 < 8; i2++) {
        int t = tid + i2 * NT;
        int p = expandp(t);
        int p2 = 4607 - p;
        float2 Zk = z[SW(p)], Zm = z[SW(p2)];
        float2 E = make_float2(0.5f * (Zk.x + Zm.x), 0.5f * (Zk.y - Zm.y));
        float2 D = make_float2(Zk.x - Zm.x, Zk.y + Zm.y);
        float2 O = make_float2(0.5f * D.y, -0.5f * D.x);
        float2 OT = cmul(O, g_twnR[t]);
        float2 X1  = cadd(E, OT);
        float2 X2c = csub(E, OT);
        Kh[p]  = X1;
        Kh[p2] = make_float2(X2c.x, -X2c.y);
    }
}

// ---------------- main conv ------------------------------------------------------------
__global__ __launch_bounds__(NT, 4) void conv_kernel(const float* __restrict__ x,
                                                     float* __restrict__ y) {
    __shared__ float2 z[M];
    const int row = blockIdx.x;            // b*H + h
    const int h = row & (H - 1);
    const int tid = threadIdx.x;
    load_packed(z, x + (size_t)row * M, tid);
    fft_fwd(z, tid);

    const float2* __restrict__ Kh = g_Kf + (size_t)h * KSTRIDE;
    // boundary: kk ≡ 0 (mod 8)
    {
        int t = tid;
        if (t == 0) {
            float2 Z0 = z[0];
            float X0 = Z0.x + Z0.y;
            float Xm = Z0.x - Z0.y;
            float2 K0 = Kh[0], Km = Kh[M];
            float2 Y0 = make_float2(X0 * K0.x, X0 * K0.y);
            float2 Ym = make_float2(Xm * Km.x, Xm * Km.y);
            float2 Ey = make_float2(0.5f * (Y0.x + Ym.x), 0.5f * (Y0.y - Ym.y));
            float2 Oy = make_float2(0.5f * (Y0.x - Ym.x), 0.5f * (Y0.y + Ym.y));
            z[0] = make_float2(Ey.x - Oy.y, Ey.y + Oy.x);  // Ey + i*Oy
            float2 Zh = z[SW(4)];
            z[SW(4)] = cmulc(Zh, Kh[4]);                    // bin M/2
        } else {
            int kk = 8 * t;
            int pa = rev8(kk), pb = rev8(M - kk);
            int spa = SW(pa), spb = SW(pb);
            float2 Zk = z[spa], Zm = z[spb];
            float2 tw = g_twm[4 * t];
            float2 E = make_float2(0.5f * (Zk.x + Zm.x), 0.5f * (Zk.y - Zm.y));
            float2 D = make_float2(Zk.x - Zm.x, Zk.y + Zm.y);
            float2 O = make_float2(0.5f * D.y, -0.5f * D.x);
            float2 OT = cmul(O, tw);
            float2 X1  = cadd(E, OT);
            float2 X2c = csub(E, OT);
            float2 K1 = Kh[pa], K2 = Kh[pb];
            float2 Y1  = cmul(X1, K1);
            float2 Y2c = cmulc(X2c, K2);
            float2 Ey = make_float2(0.5f * (Y1.x + Y2c.x), 0.5f * (Y1.y + Y2c.y));
            float2 G  = make_float2(0.5f * (Y1.x - Y2c.x), 0.5f * (Y1.y - Y2c.y));
            float2 Oy = cmulc(G, tw);
            z[spa] = make_float2(Ey.x - Oy.y, Ey.y + Oy.x);
            z[spb] = make_float2(Ey.x + Oy.y, Oy.x - Ey.y);
        }
    }
    // main: conflict-free positions
#pragma unroll
    for (int i2 = 1; i2 < 8; i2++) {
        int t = tid + i2 * NT;
        int p = expandp(t);
        int p2 = 4607 - p;
        int sp = SW(p), sp2 = SW(p2);
        float2 Zk = z[sp], Zm = z[sp2];
        float2 tw = g_twnR[t];
        float2 E = make_float2(0.5f * (Zk.x + Zm.x), 0.5f * (Zk.y - Zm.y));
        float2 D = make_float2(Zk.x - Zm.x, Zk.y + Zm.y);
        float2 O = make_float2(0.5f * D.y, -0.5f * D.x);
        float2 OT = cmul(O, tw);
        float2 X1  = cadd(E, OT);
        float2 X2c = csub(E, OT);
        float2 K1 = Kh[p], K2 = Kh[p2];
        float2 Y1  = cmul(X1, K1);
        float2 Y2c = cmulc(X2c, K2);
        float2 Ey = make_float2(0.5f * (Y1.x + Y2c.x), 0.5f * (Y1.y + Y2c.y));
        float2 G  = make_float2(0.5f * (Y1.x - Y2c.x), 0.5f * (Y1.y - Y2c.y));
        float2 Oy = cmulc(G, tw);
        z[sp]  = make_float2(Ey.x - Oy.y, Ey.y + Oy.x);
        z[sp2] = make_float2(Ey.x + Oy.y, Oy.x - Ey.y);
    }
    __syncthreads();
    fft_inv(z, tid);

    const float scale = 1.0f / (float)M;
    float4* yrow4 = (float4*)(y + (size_t)row * M);
    for (int j = tid; j < M / 4; j += NT) {
        float2 v0 = z[SW(2 * j)];
        float2 v1 = z[SW(2 * j + 1)];
        yrow4[j] = make_float4(v0.x * scale, v0.y * scale, v1.x * scale, v1.y * scale);
    }
}

extern "C" void kernel_launch(void* const* d_in, const int* in_sizes, int n_in,
                              void* d_out, int out_size) {
    const float* x;
    const float* k;
    if (in_sizes[0] == B * H * M) {           // x is the larger tensor
        x = (const float*)d_in[0];
        k = (const float*)d_in[1];
    } else {
        x = (const float*)d_in[1];
        k = (const float*)d_in[0];
    }
    float* y = (float*)d_out;

    init_twiddles<<<(M + M / 2 + 511) / 512, 512>>>();
    kf_kernel<<<H, NT>>>(k);
    conv_kernel<<<B * H, NT>>>(x, y);
}

// round 6
// speedup vs baseline: 1.0967x; 1.0967x over previous
#include <cuda_runtime.h>

// FFT convolution (S4): y[b,0,h,:] = first 4096 samples of linear conv(x[b,h,:], k[0,h,:])
// via length-8192 real FFT implemented as 4096-pt complex FFT with even/odd packing.
//
// R5: radix-16 FFT (3 stages instead of 4) — smem-bandwidth-bound kernel, so fewer
// passes at equal flops. New conflict-free XOR swizzle for strides 1/16/256, t-ordered
// coalesced K_f layout, pruned first-fwd/last-inv stages, constant-twiddle DFT16.

#define M 4096
#define H 1024
#define B 4
#define NT 256
#define NPAIR 1920           // pairs with kk !≡ 0 (mod 16), kk < 2048

#define PHI(a) ((a) ^ (((a) >> 4) & 15) ^ ((((a) >> 8) & 15) << 4))

__device__ float2 g_twm[M];              // e^{-2pi i e / M}
__device__ float2 g_twnT[NPAIR];         // e^{-pi i kk(t) / M}, t-ordered
__device__ float2 g_KfA[H * NPAIR];      // Kf[h][kk(t)]
__device__ float2 g_KfB[H * NPAIR];      // Kf[h][M-kk(t)]
__device__ float2 g_KfC[H * 128];        // u=0: (Kf[0].re, Kf[M].re); u>0: Kf[16u]
__device__ float2 g_KfD[H * 128];        // u=0: Kf[M/2];              u>0: Kf[M-16u]

__device__ __forceinline__ float2 cadd(float2 a, float2 b) { return make_float2(a.x + b.x, a.y + b.y); }
__device__ __forceinline__ float2 csub(float2 a, float2 b) { return make_float2(a.x - b.x, a.y - b.y); }
__device__ __forceinline__ float2 cmul(float2 a, float2 b) {
    return make_float2(fmaf(a.x, b.x, -a.y * b.y), fmaf(a.x, b.y, a.y * b.x));
}
__device__ __forceinline__ float2 cmulc(float2 a, float2 b) {  // a * conj(b)
    return make_float2(fmaf(a.x, b.x, a.y * b.y), fmaf(a.y, b.x, -a.x * b.y));
}
__device__ __forceinline__ float2 cmulK(float2 a, float cr, float ci) {
    return make_float2(fmaf(a.x, cr, -a.y * ci), fmaf(a.x, ci, a.y * cr));
}

#define CC 0.70710678118654752f

// cos/sin(k*pi/8), k = 0..9
__device__ __constant__ float W16C[10] = {1.f, 0.92387953251f, 0.70710678119f, 0.38268343236f, 0.f,
                                          -0.38268343236f, -0.70710678119f, -0.92387953251f, -1.f, -0.92387953251f};
__device__ __constant__ float W16S[10] = {0.f, 0.38268343236f, 0.70710678119f, 0.92387953251f, 1.f,
                                          0.92387953251f, 0.70710678119f, 0.38268343236f, 0.f, -0.38268343236f};

// kk(t) for the t-ordered pair enumeration (c1 fastest for conflict-free smem)
__device__ __forceinline__ void pair_digits(int t, int& c0, int& c1, int& c2) {
    c0 = 1 + (t >> 7);         // 1..15
    c1 = t & 15;               // 0..15
    c2 = (t >> 4) & 7;         // 0..7
}

__global__ void init_twiddles() {
    int i = blockIdx.x * blockDim.x + threadIdx.x;
    if (i < M) {
        float s, c;
        sincospif(-2.0f * (float)i / (float)M, &s, &c);
        g_twm[i] = make_float2(c, s);
    }
    int t = i - M;
    if (t >= 0 && t < NPAIR) {
        int c0, c1, c2; pair_digits(t, c0, c1, c2);
        int kk = 256 * c2 + 16 * c1 + c0;
        float s, c;
        sincospif(-(float)kk / (float)M, &s, &c);
        g_twnT[t] = make_float2(c, s);
    }
}

// ---------------- building blocks -----------------------------------------------------

template <bool FWD>
__device__ __forceinline__ void dft4(float2& A, float2& Bv, float2& Cv, float2& D) {
    float2 t0 = cadd(A, Cv), t1 = csub(A, Cv), t2 = cadd(Bv, D), t3 = csub(Bv, D);
    A = cadd(t0, t2); Cv = csub(t0, t2);
    if (FWD) {
        Bv = make_float2(t1.x + t3.y, t1.y - t3.x);
        D  = make_float2(t1.x - t3.y, t1.y + t3.x);
    } else {
        Bv = make_float2(t1.x - t3.y, t1.y + t3.x);
        D  = make_float2(t1.x + t3.y, t1.y - t3.x);
    }
}

template <bool FWD, int E>
__device__ __forceinline__ float2 cw16(float2 a) {
    if (E == 4) return FWD ? make_float2(a.y, -a.x) : make_float2(-a.y, a.x);
    const float cr = W16C[E];
    const float ci = FWD ? -W16S[E] : W16S[E];
    return cmulK(a, cr, ci);
}

// in-register 16-pt DFT; output: slot (m&3)*4 + (m>>2) holds X[m]
template <bool FWD>
__device__ __forceinline__ void dft16(float2* r) {
    dft4<FWD>(r[0], r[4], r[8], r[12]);
    dft4<FWD>(r[1], r[5], r[9], r[13]);
    dft4<FWD>(r[2], r[6], r[10], r[14]);
    dft4<FWD>(r[3], r[7], r[11], r[15]);
    r[5]  = cw16<FWD, 1>(r[5]);
    r[9]  = cw16<FWD, 2>(r[9]);
    r[13] = cw16<FWD, 3>(r[13]);
    r[6]  = cw16<FWD, 2>(r[6]);
    r[10] = cw16<FWD, 4>(r[10]);
    r[14] = cw16<FWD, 6>(r[14]);
    r[7]  = cw16<FWD, 3>(r[7]);
    r[11] = cw16<FWD, 6>(r[11]);
    r[15] = cw16<FWD, 9>(r[15]);
    dft4<FWD>(r[0],  r[1],  r[2],  r[3]);
    dft4<FWD>(r[4],  r[5],  r[6],  r[7]);
    dft4<FWD>(r[8],  r[9],  r[10], r[11]);
    dft4<FWD>(r[12], r[13], r[14], r[15]);
}
#define X16(r, m) (r)[(((m) & 3) << 2) | ((m) >> 2)]

__device__ __forceinline__ void dft8f(float2* a) {
    float2 s0 = cadd(a[0], a[4]), s1 = csub(a[0], a[4]), s2 = cadd(a[2], a[6]), s3 = csub(a[2], a[6]);
    float2 E0 = cadd(s0, s2), E2 = csub(s0, s2);
    float2 E1 = make_float2(s1.x + s3.y, s1.y - s3.x);
    float2 E3 = make_float2(s1.x - s3.y, s1.y + s3.x);
    float2 t0 = cadd(a[1], a[5]), t1 = csub(a[1], a[5]), t2 = cadd(a[3], a[7]), t3 = csub(a[3], a[7]);
    float2 O0 = cadd(t0, t2), O2 = csub(t0, t2);
    float2 O1 = make_float2(t1.x + t3.y, t1.y - t3.x);
    float2 O3 = make_float2(t1.x - t3.y, t1.y + t3.x);
    float2 P1 = make_float2(CC * (O1.x + O1.y), CC * (O1.y - O1.x));
    float2 P2 = make_float2(O2.y, -O2.x);
    float2 P3 = make_float2(CC * (O3.y - O3.x), -CC * (O3.x + O3.y));
    a[0] = cadd(E0, O0); a[4] = csub(E0, O0);
    a[1] = cadd(E1, P1); a[5] = csub(E1, P1);
    a[2] = cadd(E2, P2); a[6] = csub(E2, P2);
    a[3] = cadd(E3, P3); a[7] = csub(E3, P3);
}

__device__ __forceinline__ void dft8i(float2* a) {
    float2 s0 = cadd(a[0], a[4]), s1 = csub(a[0], a[4]), s2 = cadd(a[2], a[6]), s3 = csub(a[2], a[6]);
    float2 E0 = cadd(s0, s2), E2 = csub(s0, s2);
    float2 E1 = make_float2(s1.x - s3.y, s1.y + s3.x);
    float2 E3 = make_float2(s1.x + s3.y, s1.y - s3.x);
    float2 t0 = cadd(a[1], a[5]), t1 = csub(a[1], a[5]), t2 = cadd(a[3], a[7]), t3 = csub(a[3], a[7]);
    float2 O0 = cadd(t0, t2), O2 = csub(t0, t2);
    float2 O1 = make_float2(t1.x - t3.y, t1.y + t3.x);
    float2 O3 = make_float2(t1.x + t3.y, t1.y - t3.x);
    float2 P1 = make_float2(CC * (O1.x - O1.y), CC * (O1.x + O1.y));
    float2 P2 = make_float2(-O2.y, O2.x);
    float2 P3 = make_float2(-CC * (O3.x + O3.y), CC * (O3.x - O3.y));
    a[0] = cadd(E0, O0); a[4] = csub(E0, O0);
    a[1] = cadd(E1, P1); a[5] = csub(E1, P1);
    a[2] = cadd(E2, P2); a[6] = csub(E2, P2);
    a[3] = cadd(E3, P3); a[7] = csub(E3, P3);
}

// stage twiddle powers: stored {w1,w2,w3,w4,w8,w12}, others 1 cmul away
struct TwSet { float2 w1, w2, w3, w4, w8, w12; };
__device__ __forceinline__ TwSet mktw(float2 w1) {
    TwSet T;
    T.w1 = w1;
    T.w2 = cmul(w1, w1);
    T.w3 = cmul(T.w2, w1);
    T.w4 = cmul(T.w2, T.w2);
    T.w8 = cmul(T.w4, T.w4);
    T.w12 = cmul(T.w8, T.w4);
    return T;
}
template <int P>
__device__ __forceinline__ float2 twpow(const TwSet& T) {
    if (P == 1) return T.w1;
    if (P == 2) return T.w2;
    if (P == 3) return T.w3;
    if (P == 4) return T.w4;
    if (P == 5) return cmul(T.w4, T.w1);
    if (P == 6) return cmul(T.w4, T.w2);
    if (P == 7) return cmul(T.w4, T.w3);
    if (P == 8) return T.w8;
    if (P == 9) return cmul(T.w8, T.w1);
    if (P == 10) return cmul(T.w8, T.w2);
    if (P == 11) return cmul(T.w8, T.w3);
    if (P == 12) return T.w12;
    if (P == 13) return cmul(T.w12, T.w1);
    if (P == 14) return cmul(T.w12, T.w2);
    return cmul(T.w12, T.w3);
}

// ---------------- stages (NT=256, 1 butterfly per thread per stage) --------------------

// fwd L=4096 (q=256, twstep=1), inputs k>=8 are zero (pruned)
__device__ __forceinline__ void fwd_stage1(float2* __restrict__ z, int t) {
    const int d0 = t & 15, d1 = (t >> 4) & 15;
    const int C = (d0 ^ d1) | (d1 << 4);
    float2 a[8], b[8];
#pragma unroll
    for (int k = 0; k < 8; k++) a[k] = z[C ^ ((k << 4) ^ (k << 8))];
    b[0] = a[0];
#pragma unroll
    for (int k = 1; k < 8; k++) b[k] = cmulK(a[k], W16C[k], -W16S[k]);
    dft8f(a);   // X[2r]
    dft8f(b);   // X[2r+1]
    TwSet T = mktw(g_twm[t]);
    z[C] = a[0];
#define ST1(m) z[C ^ (((m) << 4) ^ ((m) << 8))] = cmul(((m) & 1) ? b[(m) >> 1] : a[(m) >> 1], twpow<m>(T))
    ST1(1); ST1(2); ST1(3); ST1(4); ST1(5); ST1(6); ST1(7); ST1(8);
    ST1(9); ST1(10); ST1(11); ST1(12); ST1(13); ST1(14); ST1(15);
#undef ST1
}

// fwd L=256 (q=16, twstep=16)
__device__ __forceinline__ void fwd_stage2(float2* __restrict__ z, int t) {
    const int bb = t >> 4, j = t & 15;
    const int C = j | (bb << 4) | (bb << 8);
    float2 r[16];
#pragma unroll
    for (int k = 0; k < 16; k++) r[k] = z[C ^ (17 * k)];
    dft16<true>(r);
    TwSet T = mktw(g_twm[j << 4]);
    z[C] = r[0];
#define ST2(m) z[C ^ (17 * (m))] = cmul(X16(r, m), twpow<m>(T))
    ST2(1); ST2(2); ST2(3); ST2(4); ST2(5); ST2(6); ST2(7); ST2(8);
    ST2(9); ST2(10); ST2(11); ST2(12); ST2(13); ST2(14); ST2(15);
#undef ST2
}

// fwd L=16 (q=1, no twiddles)
__device__ __forceinline__ void fwd_stage3(float2* __restrict__ z, int t) {
    const int bl = t & 15, bh = t >> 4;
    const int C = bl | (((bl ^ bh) & 15) << 4) | (bh << 8);
    float2 r[16];
#pragma unroll
    for (int k = 0; k < 16; k++) r[k] = z[C ^ k];
    dft16<true>(r);
#pragma unroll
    for (int m = 0; m < 16; m++) z[C ^ m] = X16(r, m);
}

// inv L=16 (no twiddles)
__device__ __forceinline__ void inv_stage1(float2* __restrict__ z, int t) {
    const int bl = t & 15, bh = t >> 4;
    const int C = bl | (((bl ^ bh) & 15) << 4) | (bh << 8);
    float2 r[16];
#pragma unroll
    for (int k = 0; k < 16; k++) r[k] = z[C ^ k];
    dft16<false>(r);
#pragma unroll
    for (int m = 0; m < 16; m++) z[C ^ m] = X16(r, m);
}

// inv L=256 (conj twiddles on inputs)
__device__ __forceinline__ void inv_stage2(float2* __restrict__ z, int t) {
    const int bb = t >> 4, j = t & 15;
    const int C = j | (bb << 4) | (bb << 8);
    TwSet T = mktw(g_twm[j << 4]);
    float2 r[16];
    r[0] = z[C];
#define LD2(k) r[k] = cmulc(z[C ^ (17 * (k))], twpow<k>(T))
    LD2(1); LD2(2); LD2(3); LD2(4); LD2(5); LD2(6); LD2(7); LD2(8);
    LD2(9); LD2(10); LD2(11); LD2(12); LD2(13); LD2(14); LD2(15);
#undef LD2
    dft16<false>(r);
#pragma unroll
    for (int m = 0; m < 16; m++) z[C ^ (17 * m)] = X16(r, m);
}

// inv L=4096 (conj twiddles on inputs; only outputs k<8 kept)
__device__ __forceinline__ void inv_stage3(float2* __restrict__ z, int t) {
    const int d0 = t & 15, d1 = (t >> 4) & 15;
    const int C = (d0 ^ d1) | (d1 << 4);
    TwSet T = mktw(g_twm[t]);
    float2 ae[8], ao[8];
    ae[0] = z[C];
#define LD3(k) { float2 v = cmulc(z[C ^ (((k) << 4) ^ ((k) << 8))], twpow<k>(T)); \
                 if ((k) & 1) ao[(k) >> 1] = v; else ae[(k) >> 1] = v; }
    LD3(1); LD3(2); LD3(3); LD3(4); LD3(5); LD3(6); LD3(7); LD3(8);
    LD3(9); LD3(10); LD3(11); LD3(12); LD3(13); LD3(14); LD3(15);
#undef LD3
    dft8i(ae);
    dft8i(ao);
#pragma unroll
    for (int k = 0; k < 8; k++) {
        float2 v = cadd(ae[k], cmulK(ao[k], W16C[k], W16S[k]));   // + v16^k * O
        z[C ^ ((k << 4) ^ (k << 8))] = v;
    }
}

// load packed real row (x[2j], x[2j+1]) -> z[j], lower half only (upper pruned)
__device__ __forceinline__ void load_packed(float2* z, const float* src, int tid) {
    const float4* s4 = (const float4*)src;
#pragma unroll
    for (int it = 0; it < (M / 4) / NT; it++) {
        int j = tid + it * NT;
        float4 v = s4[j];
        z[PHI(2 * j)]     = make_float2(v.x, v.y);
        z[PHI(2 * j + 1)] = make_float2(v.z, v.w);
    }
    __syncthreads();
}

// ---------------- kernel spectra -------------------------------------------------------
__global__ __launch_bounds__(NT, 3) void kf_kernel(const float* __restrict__ kin) {
    __shared__ float2 z[M];
    const int h = blockIdx.x;
    const int tid = threadIdx.x;
    load_packed(z, kin + (size_t)h * M, tid);
    fwd_stage1(z, tid); __syncthreads();
    fwd_stage2(z, tid); __syncthreads();
    fwd_stage3(z, tid); __syncthreads();

    // boundary bins kk ≡ 0 (mod 16)
    if (tid < 128) {
        int u = tid;
        if (u == 0) {
            float2 Z0 = z[0];
            g_KfC[h * 128] = make_float2(Z0.x + Z0.y, Z0.x - Z0.y);  // (Kf[0].re, Kf[M].re)
            float2 Zh = z[8];                                        // pos of bin M/2
            g_KfD[h * 128] = make_float2(Zh.x, -Zh.y);               // Kf[M/2]
        } else {
            int p = 16 * (u & 15) + (u >> 4);
            int w = 256 - u;
            int q = 16 * (w & 15) + ((w >> 4) & 15);
            float2 Zk = z[PHI(p)], Zm = z[PHI(q)];
            float2 E = make_float2(0.5f * (Zk.x + Zm.x), 0.5f * (Zk.y - Zm.y));
            float2 D = make_float2(Zk.x - Zm.x, Zk.y + Zm.y);
            float2 O = make_float2(0.5f * D.y, -0.5f * D.x);
            float2 OT = cmul(O, g_twm[u << 3]);
            float2 X1  = cadd(E, OT);
            float2 X2c = csub(E, OT);
            g_KfC[h * 128 + u] = X1;                             // Kf[16u]
            g_KfD[h * 128 + u] = make_float2(X2c.x, -X2c.y);     // Kf[M-16u]
        }
    }
    // main pairs
    for (int t = tid; t < NPAIR; t += NT) {
        int c0, c1, c2; pair_digits(t, c0, c1, c2);
        int p = 256 * c0 + 16 * c1 + c2;
        int q = 4351 - p;
        float2 Zk = z[PHI(p)], Zm = z[PHI(q)];
        float2 E = make_float2(0.5f * (Zk.x + Zm.x), 0.5f * (Zk.y - Zm.y));
        float2 D = make_float2(Zk.x - Zm.x, Zk.y + Zm.y);
        float2 O = make_float2(0.5f * D.y, -0.5f * D.x);
        float2 OT = cmul(O, g_twnT[t]);
        float2 X1  = cadd(E, OT);
        float2 X2c = csub(E, OT);
        g_KfA[h * NPAIR + t] = X1;                              // Kf[kk]
        g_KfB[h * NPAIR + t] = make_float2(X2c.x, -X2c.y);      // Kf[M-kk]
    }
}

// ---------------- main conv ------------------------------------------------------------
__global__ __launch_bounds__(NT, 3) void conv_kernel(const float* __restrict__ x,
                                                     float* __restrict__ y) {
    __shared__ float2 z[M];
    const int row = blockIdx.x;            // b*H + h
    const int h = row & (H - 1);
    const int tid = threadIdx.x;
    load_packed(z, x + (size_t)row * M, tid);
    fwd_stage1(z, tid); __syncthreads();
    fwd_stage2(z, tid); __syncthreads();
    fwd_stage3(z, tid); __syncthreads();

    // boundary bins kk ≡ 0 (mod 16)
    if (tid < 128) {
        int u = tid;
        if (u == 0) {
            float2 Z0 = z[0];
            float X0 = Z0.x + Z0.y;
            float Xm = Z0.x - Z0.y;
            float2 Kc = g_KfC[h * 128];
            float Y0 = X0 * Kc.x;
            float Ym = Xm * Kc.y;
            z[0] = make_float2(0.5f * (Y0 + Ym), 0.5f * (Y0 - Ym));
            float2 Zh = z[8];
            z[8] = cmulc(Zh, g_KfD[h * 128]);                   // bin M/2
        } else {
            int p = 16 * (u & 15) + (u >> 4);
            int w = 256 - u;
            int q = 16 * (w & 15) + ((w >> 4) & 15);
            int sp = PHI(p), sq = PHI(q);
            float2 Zk = z[sp], Zm = z[sq];
            float2 tw = g_twm[u << 3];
            float2 E = make_float2(0.5f * (Zk.x + Zm.x), 0.5f * (Zk.y - Zm.y));
            float2 D = make_float2(Zk.x - Zm.x, Zk.y + Zm.y);
            float2 O = make_float2(0.5f * D.y, -0.5f * D.x);
            float2 OT = cmul(O, tw);
            float2 X1  = cadd(E, OT);
            float2 X2c = csub(E, OT);
            float2 K1 = g_KfC[h * 128 + u], K2 = g_KfD[h * 128 + u];
            float2 Y1  = cmul(X1, K1);
            float2 Y2c = cmulc(X2c, K2);
            float2 Ey = make_float2(0.5f * (Y1.x + Y2c.x), 0.5f * (Y1.y + Y2c.y));
            float2 G  = make_float2(0.5f * (Y1.x - Y2c.x), 0.5f * (Y1.y - Y2c.y));
            float2 Oy = cmulc(G, tw);
            z[sp] = make_float2(Ey.x - Oy.y, Ey.y + Oy.x);
            z[sq] = make_float2(Ey.x + Oy.y, Oy.x - Ey.y);
        }
    }
    // main pairs
    for (int t = tid; t < NPAIR; t += NT) {
        int c0, c1, c2; pair_digits(t, c0, c1, c2);
        int p = 256 * c0 + 16 * c1 + c2;
        int q = 4351 - p;
        int sp = PHI(p), sq = PHI(q);
        float2 Zk = z[sp], Zm = z[sq];
        float2 tw = g_twnT[t];
        float2 E = make_float2(0.5f * (Zk.x + Zm.x), 0.5f * (Zk.y - Zm.y));
        float2 D = make_float2(Zk.x - Zm.x, Zk.y + Zm.y);
        float2 O = make_float2(0.5f * D.y, -0.5f * D.x);
        float2 OT = cmul(O, tw);
        float2 X1  = cadd(E, OT);
        float2 X2c = csub(E, OT);
        float2 K1 = g_KfA[h * NPAIR + t], K2 = g_KfB[h * NPAIR + t];
        float2 Y1  = cmul(X1, K1);
        float2 Y2c = cmulc(X2c, K2);
        float2 Ey = make_float2(0.5f * (Y1.x + Y2c.x), 0.5f * (Y1.y + Y2c.y));
        float2 G  = make_float2(0.5f * (Y1.x - Y2c.x), 0.5f * (Y1.y - Y2c.y));
        float2 Oy = cmulc(G, tw);
        z[sp] = make_float2(Ey.x - Oy.y, Ey.y + Oy.x);
        z[sq] = make_float2(Ey.x + Oy.y, Oy.x - Ey.y);
    }
    __syncthreads();
    inv_stage1(z, tid); __syncthreads();
    inv_stage2(z, tid); __syncthreads();
    inv_stage3(z, tid); __syncthreads();

    const float scale = 1.0f / (float)M;
    float4* yrow4 = (float4*)(y + (size_t)row * M);
#pragma unroll
    for (int it = 0; it < (M / 4) / NT; it++) {
        int j = tid + it * NT;
        float2 v0 = z[PHI(2 * j)];
        float2 v1 = z[PHI(2 * j + 1)];
        yrow4[j] = make_float4(v0.x * scale, v0.y * scale, v1.x * scale, v1.y * scale);
    }
}

extern "C" void kernel_launch(void* const* d_in, const int* in_sizes, int n_in,
                              void* d_out, int out_size) {
    const float* x;
    const float* k;
    if (in_sizes[0] == B * H * M) {           // x is the larger tensor
        x = (const float*)d_in[0];
        k = (const float*)d_in[1];
    } else {
        x = (const float*)d_in[1];
        k = (const float*)d_in[0];
    }
    float* y = (float*)d_out;

    init_twiddles<<<(M + NPAIR + 511) / 512, 512>>>();
    kf_kernel<<<H, NT>>>(k);
    conv_kernel<<<B * H, NT>>>(x, y);
}